// round 16
// baseline (speedup 1.0000x reference)
#include <cuda_runtime.h>
#include <cuda_bf16.h>

// Problem constants (fixed by the reference)
#define BB      2
#define XX      200
#define YY      200
#define ZZ      16      // == HEIGHT, h = 1
#define CC      17
#define EMPTY_LABEL 16
#define CHOOSE  4000

#define TPB 256
#define COLS_PER_BLK 16
#define BLKS_PER_B (CHOOSE / COLS_PER_BLK)    // 250
#define GRID (BB * BLKS_PER_B)                // 500  (single wave: < 148*8)

#define LEAVES 32
#define LEAF_STRIDE 16                        // 16 u64 = 128B (distinct L2 lines)
#define LAST_LEAF_TGT (GRID - (LEAVES - 1) * 16)   // 4

// Persistent device scratch (allocation-free).
// g_cnt_part / g_loss_part: per-block OWN slots, plain stores, overwritten
// before use every call (no reset needed). Leaf/root counters are MONOTONIC
// epoch counters (never reset); epoch = arrival_return / per_leaf_target.
__device__ uint4               g_cnt_part[GRID];
__device__ float               g_loss_part[GRID];
__device__ unsigned long long  g_leaf1[LEAVES * LEAF_STRIDE];
__device__ unsigned long long  g_root1;
__device__ unsigned long long  g_leaf2[LEAVES * LEAF_STRIDE];
__device__ unsigned long long  g_root2;

__device__ __forceinline__ void cp16(unsigned smem_addr, const void* gptr) {
    asm volatile("cp.async.cg.shared.global [%0], [%1], 16;"
                 :: "r"(smem_addr), "l"(gptr));
}

// ---------------------------------------------------------------------------
__global__ void __launch_bounds__(TPB)
fused_loss(const float* __restrict__ preds,
           const int*   __restrict__ labels,
           const int*   __restrict__ sel,
           float*       __restrict__ out) {
    const int bid = blockIdx.x;
    const int tid = threadIdx.x;
    const int b  = bid / BLKS_PER_B;
    const int cb = bid % BLKS_PER_B;
    const int w    = tid >> 5;
    const int lane = tid & 31;
    const int leaf = bid >> 4;                       // 0..31
    const int ltgt = (leaf == LEAVES - 1) ? LAST_LEAF_TGT : 16;

    __shared__ float s_pred[COLS_PER_BLK * ZZ * CC];   // 17408B
    __shared__ int   s_lab [COLS_PER_BLK * ZZ];        // 1KB
    __shared__ int   s_zcnt[ZZ];
    __shared__ unsigned s_part[8 * 8];                 // 8 warps x 8 u32 fields
    __shared__ int   s_czv[ZZ];
    __shared__ float s_wsum[TPB / 32];
    __shared__ int   s_n1;

    if (tid < ZZ) s_zcnt[tid] = 0;

    // ---- sel for this warp's 2 columns (lanes 0,1), broadcast --------------
    int colv = 0;
    if (lane < 2) {
        int2 xy = __ldg((const int2*)sel + b * CHOOSE + cb * COLS_PER_BLK + 2 * w + lane);
        colv = (b * XX + xy.x) * YY + xy.y;
    }
    const int colA = __shfl_sync(0xffffffffu, colv, 0);
    const int colB = __shfl_sync(0xffffffffu, colv, 1);

    // ---- group 0: labels (needed first, for counts) -------------------------
    if (lane < 8) {
        int c = (lane < 4) ? colA : colB;
        unsigned dl = (unsigned)__cvta_generic_to_shared(
                          s_lab + (2 * w + (lane >> 2)) * ZZ) + (lane & 3) * 16;
        cp16(dl, (const int4*)(labels + (long long)c * ZZ) + (lane & 3));
    }
    asm volatile("cp.async.commit_group;");

    // ---- group 1: preds (2 x 1088B per warp) --------------------------------
    {
        const float4* __restrict__ srcA = (const float4*)preds + (long long)colA * 68;
        const float4* __restrict__ srcB = (const float4*)preds + (long long)colB * 68;
        unsigned dstA = (unsigned)__cvta_generic_to_shared(s_pred + (2 * w)     * (ZZ * CC));
        unsigned dstB = (unsigned)__cvta_generic_to_shared(s_pred + (2 * w + 1) * (ZZ * CC));
        cp16(dstA + lane * 16,        srcA + lane);
        cp16(dstB + lane * 16,        srcB + lane);
        cp16(dstA + (lane + 32) * 16, srcA + lane + 32);
        cp16(dstB + (lane + 32) * 16, srcB + lane + 32);
        if (lane < 4) {
            cp16(dstA + (lane + 64) * 16, srcA + lane + 64);
            cp16(dstB + (lane + 64) * 16, srcB + lane + 64);
        }
        asm volatile("cp.async.commit_group;");
    }

    // ---- wait labels only (preds keep flying); per-block counts -------------
    asm volatile("cp.async.wait_group 1;");
    __syncwarp();

    const int z   = lane & 15;
    const int lcl = lane >> 4;
    const int lab = s_lab[(2 * w + lcl) * ZZ + z];
    const bool valid = (lab != EMPTY_LABEL);

    unsigned bal = __ballot_sync(0xffffffffu, valid);
    if (lane < ZZ) {
        int c2 = __popc(bal & ((1u << lane) | (1u << (lane + 16))));
        if (c2) atomicAdd(&s_zcnt[lane], c2);      // smem agg only
    }
    __syncthreads();

    // ---- pack 16 byte-counts -> OWN slot (plain STG.128, NO global atomic) --
    if (tid == 0) {
        uint4 pk;
        pk.x = (unsigned)s_zcnt[0]  | ((unsigned)s_zcnt[1]  << 8) |
               ((unsigned)s_zcnt[2]  << 16) | ((unsigned)s_zcnt[3]  << 24);
        pk.y = (unsigned)s_zcnt[4]  | ((unsigned)s_zcnt[5]  << 8) |
               ((unsigned)s_zcnt[6]  << 16) | ((unsigned)s_zcnt[7]  << 24);
        pk.z = (unsigned)s_zcnt[8]  | ((unsigned)s_zcnt[9]  << 8) |
               ((unsigned)s_zcnt[10] << 16) | ((unsigned)s_zcnt[11] << 24);
        pk.w = (unsigned)s_zcnt[12] | ((unsigned)s_zcnt[13] << 8) |
               ((unsigned)s_zcnt[14] << 16) | ((unsigned)s_zcnt[15] << 24);
        g_cnt_part[bid] = pk;
        __threadfence();                            // release slot

        // -- barrier 1: tree arrival (<=16 ops/leaf, 32 ops on root) ----------
        unsigned long long old = atomicAdd(&g_leaf1[leaf * LEAF_STRIDE], 1ULL);
        if (old % (unsigned long long)ltgt == (unsigned long long)(ltgt - 1)) {
            __threadfence();
            atomicAdd(&g_root1, 1ULL);
        }
        unsigned long long rt = (old / (unsigned long long)ltgt + 1ULL) * LEAVES;
        volatile unsigned long long* vr = (volatile unsigned long long*)&g_root1;
        while (*vr < rt) { __nanosleep(32); }
        __threadfence();                            // acquire all slots
    }
    __syncthreads();

    // ---- re-reduce my batch's 250 slots (SIMD 16-bit fields) ----------------
    {
        const uint4* __restrict__ pb = g_cnt_part + b * BLKS_PER_B;
        const int slot = w * 32 + lane;
        uint4 q = make_uint4(0, 0, 0, 0);
        if (slot < BLKS_PER_B) q = pb[slot];
        unsigned a0 = q.x & 0x00FF00FFu, a1 = (q.x >> 8) & 0x00FF00FFu;
        unsigned a2 = q.y & 0x00FF00FFu, a3 = (q.y >> 8) & 0x00FF00FFu;
        unsigned a4 = q.z & 0x00FF00FFu, a5 = (q.z >> 8) & 0x00FF00FFu;
        unsigned a6 = q.w & 0x00FF00FFu, a7 = (q.w >> 8) & 0x00FF00FFu;
        #pragma unroll
        for (int o = 16; o > 0; o >>= 1) {
            a0 += __shfl_xor_sync(0xffffffffu, a0, o);
            a1 += __shfl_xor_sync(0xffffffffu, a1, o);
            a2 += __shfl_xor_sync(0xffffffffu, a2, o);
            a3 += __shfl_xor_sync(0xffffffffu, a3, o);
            a4 += __shfl_xor_sync(0xffffffffu, a4, o);
            a5 += __shfl_xor_sync(0xffffffffu, a5, o);
            a6 += __shfl_xor_sync(0xffffffffu, a6, o);
            a7 += __shfl_xor_sync(0xffffffffu, a7, o);
        }
        if (lane == 0) {
            s_part[w * 8 + 0] = a0; s_part[w * 8 + 1] = a1;
            s_part[w * 8 + 2] = a2; s_part[w * 8 + 3] = a3;
            s_part[w * 8 + 4] = a4; s_part[w * 8 + 5] = a5;
            s_part[w * 8 + 6] = a6; s_part[w * 8 + 7] = a7;
        }
    }
    __syncthreads();
    if (tid < ZZ) {
        const int i = tid >> 2, r = tid & 3;
        const int idx = i * 2 + (r & 1), sh = (r >> 1) * 16;
        int s = 0;
        #pragma unroll
        for (int w2 = 0; w2 < 8; w2++) s += (int)((s_part[w2 * 8 + idx] >> sh) & 0xFFFFu);
        s_czv[tid] = s;
    }
    __syncthreads();

    // ---- weights in registers ------------------------------------------------
    const int cz = s_czv[z];
    int maxc = cz;
    #pragma unroll
    for (int o = 1; o < 16; o <<= 1)
        maxc = max(maxc, __shfl_xor_sync(0xffffffffu, maxc, o));
    const float maxcf = fmaxf((float)maxc, 1.0f);
    const float LOG_RATIO = -1.0986122886681098f;   // ln(1/3)
    const float wz = (cz > 0) ? 3.0f * __expf(((float)cz / maxcf) * LOG_RATIO) : 0.0f;

    // block 0: batch-1 total via dp4a scan (overlaps softmax of other warps)
    if (bid == 0 && w == 0) {
        int acc = 0;
        const uint4* __restrict__ p1 = g_cnt_part + BLKS_PER_B;
        #pragma unroll
        for (int s2 = lane; s2 < BLKS_PER_B; s2 += 32) {
            uint4 q = p1[s2];
            acc = __dp4a((int)q.x, 0x01010101, acc);
            acc = __dp4a((int)q.y, 0x01010101, acc);
            acc = __dp4a((int)q.z, 0x01010101, acc);
            acc = __dp4a((int)q.w, 0x01010101, acc);
        }
        #pragma unroll
        for (int o = 16; o > 0; o >>= 1)
            acc += __shfl_down_sync(0xffffffffu, acc, o);
        if (lane == 0) s_n1 = acc;
    }

    // ---- preds have long since landed; softmax + smooth-L1 -------------------
    asm volatile("cp.async.wait_group 0;");
    __syncwarp();

    float val = 0.0f;
    if (valid) {
        const float* __restrict__ p = s_pred + (2 * w + lcl) * (ZZ * CC) + z * CC;
        float s = 0.0f;
        #pragma unroll
        for (int c = 0; c < CC; c++) s += __expf(p[c]);   // conflict-free LDS
        const float plab = __fdividef(__expf(p[lab]), s);
        const float ll = __logf(plab + 0.001f);
        const float wl = wz * ll;
        const float ax = fabsf(wl);
        val = (ax < 1.0f) ? 0.5f * wl * wl : (ax - 0.5f);
    }

    #pragma unroll
    for (int off = 16; off > 0; off >>= 1)
        val += __shfl_down_sync(0xffffffffu, val, off);
    if (lane == 0) s_wsum[w] = val;
    __syncthreads();

    // ---- loss -> OWN slot (plain STG); barrier-2 tree arrival -----------------
    if (tid == 0) {
        float v = 0.0f;
        #pragma unroll
        for (int i = 0; i < TPB / 32; i++) v += s_wsum[i];
        g_loss_part[bid] = v;
        __threadfence();                            // release slot

        unsigned long long old = atomicAdd(&g_leaf2[leaf * LEAF_STRIDE], 1ULL);
        if (old % (unsigned long long)ltgt == (unsigned long long)(ltgt - 1)) {
            __threadfence();
            atomicAdd(&g_root2, 1ULL);
        }
        if (bid == 0) {                             // only block 0 polls
            unsigned long long rt = (old / (unsigned long long)ltgt + 1ULL) * LEAVES;
            volatile unsigned long long* vr = (volatile unsigned long long*)&g_root2;
            while (*vr < rt) { __nanosleep(32); }
            __threadfence();                        // acquire all loss slots
        }
    }

    // ---- block 0: parallel final reduction + single write to out -------------
    if (bid == 0) {
        __syncthreads();
        float l0 = (tid < BLKS_PER_B) ? g_loss_part[tid] : 0.0f;
        float l1 = (tid < BLKS_PER_B) ? g_loss_part[BLKS_PER_B + tid] : 0.0f;
        #pragma unroll
        for (int off = 16; off > 0; off >>= 1) {
            l0 += __shfl_down_sync(0xffffffffu, l0, off);
            l1 += __shfl_down_sync(0xffffffffu, l1, off);
        }
        __shared__ float f0[8], f1[8];
        if (lane == 0) { f0[w] = l0; f1[w] = l1; }
        __syncthreads();
        if (tid == 0) {
            float L0 = 0.0f, L1 = 0.0f;
            #pragma unroll
            for (int i = 0; i < 8; i++) { L0 += f0[i]; L1 += f1[i]; }
            int n0 = 0;
            #pragma unroll
            for (int i = 0; i < ZZ; i++) n0 += s_czv[i];   // my batch (0)
            const int n1 = s_n1;
            float r0 = L0 / fmaxf((float)n0, 1.0f);
            float r1 = L1 / fmaxf((float)n1, 1.0f);
            out[0] = 0.5f * (r0 + r1);              // single writer, once
        }
    }
}

extern "C" void kernel_launch(void* const* d_in, const int* in_sizes, int n_in,
                              void* d_out, int out_size) {
    const float* preds  = nullptr;
    const int*   labels = nullptr;
    const int*   sel    = nullptr;
    for (int i = 0; i < n_in; i++) {
        if (in_sizes[i] == BB * XX * YY * ZZ * CC)      preds  = (const float*)d_in[i];
        else if (in_sizes[i] == BB * XX * YY * ZZ)      labels = (const int*)d_in[i];
        else if (in_sizes[i] == BB * CHOOSE * 2)        sel    = (const int*)d_in[i];
    }
    fused_loss<<<GRID, TPB>>>(preds, labels, sel, (float*)d_out);
}

// round 17
// speedup vs baseline: 1.0596x; 1.0596x over previous
#include <cuda_runtime.h>
#include <cuda_bf16.h>

// Problem constants (fixed by the reference)
#define BB      2
#define XX      200
#define YY      200
#define ZZ      16      // == HEIGHT, h = 1
#define CC      17
#define EMPTY_LABEL 16
#define CHOOSE  4000

#define TPB 256
#define COLS_PER_BLK 16
#define BLKS_PER_B (CHOOSE / COLS_PER_BLK)    // 250
#define GRID (BB * BLKS_PER_B)                // 500  (single wave: < 148*8)

#define LEAVES 32
#define LSTR   16                              // 16 u64 = 128B line stride
#define LAST_LEAF_TGT (GRID - (LEAVES - 1) * 16)   // 4

// Persistent device scratch (allocation-free). g_cnt / g_loss single-buffered
// (start zero; block 0 resets them after barrier 2, when all readers/writers
// are provably done; next call is stream-ordered). All counters MONOTONIC.
__device__ int                 g_cnt[BB * ZZ];
__device__ float               g_loss[BB];
__device__ unsigned long long  g_leaf1[LEAVES * LSTR];
__device__ unsigned long long  g_rel1 [LEAVES * LSTR];   // per-leaf release epoch
__device__ unsigned long long  g_root1;
__device__ unsigned long long  g_leaf2[LEAVES * LSTR];
__device__ unsigned long long  g_root2;

__device__ __forceinline__ void cp16(unsigned smem_addr, const void* gptr) {
    asm volatile("cp.async.cg.shared.global [%0], [%1], 16;"
                 :: "r"(smem_addr), "l"(gptr));
}

// ---------------------------------------------------------------------------
__global__ void __launch_bounds__(TPB)
fused_loss(const float* __restrict__ preds,
           const int*   __restrict__ labels,
           const int*   __restrict__ sel,
           float*       __restrict__ out) {
    const int bid = blockIdx.x;
    const int tid = threadIdx.x;
    const int b  = bid / BLKS_PER_B;
    const int cb = bid % BLKS_PER_B;
    const int w    = tid >> 5;
    const int lane = tid & 31;
    const int leaf = bid >> 4;
    const unsigned long long ltgt = (leaf == LEAVES - 1) ? LAST_LEAF_TGT : 16;

    __shared__ float s_pred[COLS_PER_BLK * ZZ * CC];   // 17408B
    __shared__ int   s_lab [COLS_PER_BLK * ZZ];
    __shared__ int   s_zcnt[ZZ];
    __shared__ float s_wsum[TPB / 32];
    __shared__ unsigned long long s_tgt1;

    if (tid < ZZ) s_zcnt[tid] = 0;

    // ---- sel for this warp's 2 columns (lanes 0,1), broadcast --------------
    int colv = 0;
    if (lane < 2) {
        int2 xy = __ldg((const int2*)sel + b * CHOOSE + cb * COLS_PER_BLK + 2 * w + lane);
        colv = (b * XX + xy.x) * YY + xy.y;
    }
    const int colA = __shfl_sync(0xffffffffu, colv, 0);
    const int colB = __shfl_sync(0xffffffffu, colv, 1);

    // ---- group 0: labels; group 1: preds ------------------------------------
    if (lane < 8) {
        int c = (lane < 4) ? colA : colB;
        unsigned dl = (unsigned)__cvta_generic_to_shared(
                          s_lab + (2 * w + (lane >> 2)) * ZZ) + (lane & 3) * 16;
        cp16(dl, (const int4*)(labels + (long long)c * ZZ) + (lane & 3));
    }
    asm volatile("cp.async.commit_group;");
    {
        const float4* __restrict__ srcA = (const float4*)preds + (long long)colA * 68;
        const float4* __restrict__ srcB = (const float4*)preds + (long long)colB * 68;
        unsigned dstA = (unsigned)__cvta_generic_to_shared(s_pred + (2 * w)     * (ZZ * CC));
        unsigned dstB = (unsigned)__cvta_generic_to_shared(s_pred + (2 * w + 1) * (ZZ * CC));
        cp16(dstA + lane * 16,        srcA + lane);
        cp16(dstB + lane * 16,        srcB + lane);
        cp16(dstA + (lane + 32) * 16, srcA + lane + 32);
        cp16(dstB + (lane + 32) * 16, srcB + lane + 32);
        if (lane < 4) {
            cp16(dstA + (lane + 64) * 16, srcA + lane + 64);
            cp16(dstB + (lane + 64) * 16, srcB + lane + 64);
        }
        asm volatile("cp.async.commit_group;");
    }

    // ---- labels ready; per-(b,z) counts --------------------------------------
    asm volatile("cp.async.wait_group 1;");
    __syncwarp();

    const int z   = lane & 15;
    const int lcl = lane >> 4;
    const int lab = s_lab[(2 * w + lcl) * ZZ + z];
    const bool valid = (lab != EMPTY_LABEL);

    unsigned bal = __ballot_sync(0xffffffffu, valid);
    if (lane < ZZ) {
        int c2 = __popc(bal & ((1u << lane) | (1u << (lane + 16))));
        if (c2) atomicAdd(&s_zcnt[lane], c2);
    }
    __syncthreads();

    // ---- warp 0: count REDs + barrier-1 ARRIVAL (program-ordered in warp) ----
    if (w == 0) {
        if (tid < ZZ && s_zcnt[tid]) atomicAdd(&g_cnt[b * ZZ + tid], s_zcnt[tid]);
        __threadfence();
        if (tid == 0) {
            unsigned long long old = atomicAdd(&g_leaf1[leaf * LSTR], 1ULL);
            s_tgt1 = old / ltgt + 1ULL;                 // my pass number
            if (old % ltgt == ltgt - 1ULL) {            // leaf-last -> root
                __threadfence();
                unsigned long long r = atomicAdd(&g_root1, 1ULL);
                if (r % LEAVES == LEAVES - 1ULL) {      // root-last -> release
                    unsigned long long pass = r / LEAVES + 1ULL;
                    __threadfence();
                    #pragma unroll
                    for (int i = 0; i < LEAVES; i++)
                        *(volatile unsigned long long*)&g_rel1[i * LSTR] = pass;
                }
            }
        }
    }

    // ---- preds ready; softmax ll (barrier-1 drain hides under this) ----------
    asm volatile("cp.async.wait_group 0;");
    __syncwarp();

    float ll = 0.0f;
    if (valid) {
        const float* __restrict__ p = s_pred + (2 * w + lcl) * (ZZ * CC) + z * CC;
        float s = 0.0f;
        #pragma unroll
        for (int c = 0; c < CC; c++) s += __expf(p[c]);   // conflict-free LDS
        const float plab = __fdividef(__expf(p[lab]), s);
        ll = __logf(plab + 0.001f);
    }

    // ---- NOW consume barrier 1 (poll own leaf line; <=16 pollers/line) -------
    if (tid == 0) {
        volatile unsigned long long* vr =
            (volatile unsigned long long*)&g_rel1[leaf * LSTR];
        const unsigned long long tgt = s_tgt1;
        while (*vr < tgt) { __nanosleep(64); }
        __threadfence();   // acquire: all g_cnt REDs visible
    }
    __syncthreads();

    // ---- weights ---------------------------------------------------------------
    const int cz = g_cnt[b * ZZ + z];
    int maxc = cz;
    #pragma unroll
    for (int o = 1; o < 16; o <<= 1)
        maxc = max(maxc, __shfl_xor_sync(0xffffffffu, maxc, o));
    const float maxcf = fmaxf((float)maxc, 1.0f);
    const float LOG_RATIO = -1.0986122886681098f;   // ln(1/3)
    const float wz = (cz > 0) ? 3.0f * __expf(((float)cz / maxcf) * LOG_RATIO) : 0.0f;

    int n0 = 0, n1 = 0;
    if (bid == 0 && tid == 0) {                     // totals for finalize
        #pragma unroll
        for (int z2 = 0; z2 < ZZ; z2++) { n0 += g_cnt[z2]; n1 += g_cnt[ZZ + z2]; }
    }

    // ---- smooth-L1 + block reduce ----------------------------------------------
    float val = 0.0f;
    if (valid) {
        float wl = wz * ll;
        float ax = fabsf(wl);
        val = (ax < 1.0f) ? 0.5f * wl * wl : (ax - 0.5f);
    }
    #pragma unroll
    for (int off = 16; off > 0; off >>= 1)
        val += __shfl_down_sync(0xffffffffu, val, off);
    if (lane == 0) s_wsum[w] = val;
    __syncthreads();

    // ---- loss RED + barrier-2 arrival; block 0 finalizes -------------------------
    if (tid == 0) {
        float v = 0.0f;
        #pragma unroll
        for (int i = 0; i < TPB / 32; i++) v += s_wsum[i];
        atomicAdd(&g_loss[b], v);                   // RED
        __threadfence();

        unsigned long long old = atomicAdd(&g_leaf2[leaf * LSTR], 1ULL);
        if (old % ltgt == ltgt - 1ULL) {
            __threadfence();
            atomicAdd(&g_root2, 1ULL);
        }
        if (bid == 0) {                             // sole poller of root2
            unsigned long long tgt = (old / ltgt + 1ULL) * LEAVES;
            volatile unsigned long long* vr = (volatile unsigned long long*)&g_root2;
            while (*vr < tgt) { __nanosleep(64); }
            __threadfence();                        // acquire all g_loss REDs

            float r0 = g_loss[0] / fmaxf((float)n0, 1.0f);
            float r1 = g_loss[1] / fmaxf((float)n1, 1.0f);
            out[0] = 0.5f * (r0 + r1);              // single writer, once

            // reset (all readers/writers done: barrier 2 passed)
            #pragma unroll
            for (int i = 0; i < BB * ZZ; i++) g_cnt[i] = 0;
            g_loss[0] = 0.0f;
            g_loss[1] = 0.0f;
        }
    }
}

extern "C" void kernel_launch(void* const* d_in, const int* in_sizes, int n_in,
                              void* d_out, int out_size) {
    const float* preds  = nullptr;
    const int*   labels = nullptr;
    const int*   sel    = nullptr;
    for (int i = 0; i < n_in; i++) {
        if (in_sizes[i] == BB * XX * YY * ZZ * CC)      preds  = (const float*)d_in[i];
        else if (in_sizes[i] == BB * XX * YY * ZZ)      labels = (const int*)d_in[i];
        else if (in_sizes[i] == BB * CHOOSE * 2)        sel    = (const int*)d_in[i];
    }
    fused_loss<<<GRID, TPB>>>(preds, labels, sel, (float*)d_out);
}